// round 7
// baseline (speedup 1.0000x reference)
#include <cuda_runtime.h>
#include <cuda_bf16.h>
#include <cuda_fp8.h>
#include <cstdint>
#include <cstddef>

// Problem dims (fixed)
#define NROWS 4096
#define MCOLS 4096
#define DDIM  1024

// ---------------------------------------------------------------------------
// Scratch (__device__ globals — allocation-free contract)
// ---------------------------------------------------------------------------
__device__ __nv_bfloat16 g_Hb[(size_t)NROWS * DDIM];     // H * (1/32) in bf16
__device__ __nv_bfloat16 g_Kb[(size_t)MCOLS * DDIM];     // K in bf16
__device__ uint8_t       g_Vt[(size_t)DDIM * MCOLS];     // V^T in e4m3 (K-major)
__device__ __nv_bfloat16 g_expsc[(size_t)NROWS * MCOLS]; // exp(scores) bf16
__device__ uint8_t       g_e[(size_t)NROWS * MCOLS];     // e4m3(expm1(p*mask)*4096)
__device__ float g_rsum[NROWS];
__device__ float g_z[NROWS];
__device__ float g_part[(size_t)NROWS * 128];  // GEMM1 row-sum partials [row][slot]
__device__ float g_partc[128 * DDIM];          // V colsum partials (128 row-tiles)

static __device__ __forceinline__ uint32_t smem_u32(const void* p) {
    uint32_t a;
    asm("{ .reg .u64 t; cvta.to.shared.u64 t, %1; cvt.u32.u64 %0, t; }"
        : "=r"(a) : "l"(p));
    return a;
}

static __device__ __forceinline__ uint32_t sw128(uint32_t off) {
    return off ^ ((off >> 3) & 0x70);
}

static __device__ __forceinline__ void cp16(uint32_t saddr, const void* gptr) {
    asm volatile("cp.async.cg.shared.global [%0], [%1], 16;"
                 :: "r"(saddr), "l"(gptr));
}

static __device__ __forceinline__ void cp_commit() {
    asm volatile("cp.async.commit_group;");
}

template <int N>
static __device__ __forceinline__ void cp_wait() {
    asm volatile("cp.async.wait_group %0;" :: "n"(N));
}

static __device__ __forceinline__ void ldmatrix_x4(uint32_t* r, uint32_t saddr) {
    asm volatile("ldmatrix.sync.aligned.m8n8.x4.shared.b16 {%0,%1,%2,%3}, [%4];"
                 : "=r"(r[0]), "=r"(r[1]), "=r"(r[2]), "=r"(r[3]) : "r"(saddr));
}

static __device__ __forceinline__ void mma16816(float* d, const uint32_t* a,
                                                const uint32_t* b) {
    asm volatile(
        "mma.sync.aligned.m16n8k16.row.col.f32.bf16.bf16.f32 "
        "{%0,%1,%2,%3}, {%4,%5,%6,%7}, {%8,%9}, {%0,%1,%2,%3};"
        : "+f"(d[0]), "+f"(d[1]), "+f"(d[2]), "+f"(d[3])
        : "r"(a[0]), "r"(a[1]), "r"(a[2]), "r"(a[3]), "r"(b[0]), "r"(b[1]));
}

static __device__ __forceinline__ void mma_fp8(float* d, const uint32_t* a,
                                               const uint32_t* b) {
    asm volatile(
        "mma.sync.aligned.m16n8k32.row.col.f32.e4m3.e4m3.f32 "
        "{%0,%1,%2,%3}, {%4,%5,%6,%7}, {%8,%9}, {%0,%1,%2,%3};"
        : "+f"(d[0]), "+f"(d[1]), "+f"(d[2]), "+f"(d[3])
        : "r"(a[0]), "r"(a[1]), "r"(a[2]), "r"(a[3]), "r"(b[0]), "r"(b[1]));
}

// pack 4 floats (ascending byte order) to 4 x e4m3 in one u32
static __device__ __forceinline__ uint32_t pack_e4m3x4(float f0, float f1,
                                                       float f2, float f3) {
    uint16_t lo, hi;
    asm("cvt.rn.satfinite.e4m3x2.f32 %0, %1, %2;" : "=h"(lo) : "f"(f1), "f"(f0));
    asm("cvt.rn.satfinite.e4m3x2.f32 %0, %1, %2;" : "=h"(hi) : "f"(f3), "f"(f2));
    return (uint32_t)lo | ((uint32_t)hi << 16);
}

// ===========================================================================
// GEMM1: bf16 mma.sync, 256(M) x 128(N) CTA tile, BK=64, 512 thr, 4 stages
//   epilogue: expsc = bf16(exp(acc)); deterministic row-sum partials
// ===========================================================================
#define BM1 256
#define BN1 128
#define BK1 64
#define TPB1 512
#define ST1 4
#define A1_BYTES 32768
#define B1_BYTES 16384
#define STG1_BYTES (A1_BYTES + B1_BYTES)
#define SMEM1_BYTES (ST1 * STG1_BYTES)

static __device__ __forceinline__ void issue_stage1(
    const __nv_bfloat16* __restrict__ A, const __nv_bfloat16* __restrict__ B,
    int rowBase, int colBase, int k0, uint32_t sbase, int tid) {
    uint32_t sA = sbase;
    uint32_t sB = sbase + A1_BYTES;
#pragma unroll
    for (int i = 0; i < 4; i++) {
        int l = tid + i * TPB1;
        int r = l >> 3, c = l & 7;
        uint32_t off = sw128((uint32_t)(r * 128 + c * 16));
        cp16(sA + off, A + (size_t)(rowBase + r) * DDIM + k0 + c * 8);
    }
#pragma unroll
    for (int i = 0; i < 2; i++) {
        int l = tid + i * TPB1;
        int r = l >> 3, c = l & 7;
        uint32_t off = sw128((uint32_t)(r * 128 + c * 16));
        cp16(sB + off, B + (size_t)(colBase + r) * DDIM + k0 + c * 8);
    }
}

__global__ void __launch_bounds__(TPB1, 1)
gemm1_bf16(const __nv_bfloat16* __restrict__ A, const __nv_bfloat16* __restrict__ B,
           __nv_bfloat16* __restrict__ Cb, float* __restrict__ part) {
    extern __shared__ __align__(1024) char smem[];
    uint32_t sb = smem_u32(smem);
    int tid = threadIdx.x;
    int wid = tid >> 5, lane = tid & 31;
    int wm = wid >> 2, wn = wid & 3;        // 4x4 warp grid, warp = 64m x 32n
    int rowBase = blockIdx.y * BM1;
    int colBase = blockIdx.x * BN1;
    const int nIter = DDIM / BK1;

#pragma unroll
    for (int s = 0; s < ST1 - 1; s++) {
        issue_stage1(A, B, rowBase, colBase, s * BK1, sb + s * STG1_BYTES, tid);
        cp_commit();
    }

    float acc[4][4][4];
#pragma unroll
    for (int i = 0; i < 4; i++)
#pragma unroll
        for (int j = 0; j < 4; j++)
#pragma unroll
            for (int k = 0; k < 4; k++) acc[i][j][k] = 0.f;

    int arow = wm * 64 + (lane & 15);
    int acolb = (lane >> 4) << 4;
    int brow = wn * 32 + ((lane >> 4) << 3) + (lane & 7);
    int bcolb = ((lane >> 3) & 1) << 4;

    int stage = 0;
    for (int it = 0; it < nIter; ++it) {
        cp_wait<ST1 - 2>();
        __syncthreads();
        uint32_t baseA = sb + stage * STG1_BYTES;
        uint32_t baseB = baseA + A1_BYTES;

#pragma unroll
        for (int ks = 0; ks < 4; ks++) {
            uint32_t af[4][4];
#pragma unroll
            for (int mi = 0; mi < 4; mi++) {
                uint32_t off = sw128((uint32_t)((arow + mi * 16) * 128 + ks * 32 + acolb));
                ldmatrix_x4(af[mi], baseA + off);
            }
            uint32_t bf[2][4];
#pragma unroll
            for (int ni = 0; ni < 2; ni++) {
                uint32_t off = sw128((uint32_t)((brow + ni * 16) * 128 + ks * 32 + bcolb));
                ldmatrix_x4(bf[ni], baseB + off);
            }
#pragma unroll
            for (int mi = 0; mi < 4; mi++)
#pragma unroll
                for (int ni = 0; ni < 2; ni++) {
                    mma16816(acc[mi][2 * ni], af[mi], &bf[ni][0]);
                    mma16816(acc[mi][2 * ni + 1], af[mi], &bf[ni][2]);
                }
        }

        int nxt = it + ST1 - 1;
        if (nxt < nIter) {
            issue_stage1(A, B, rowBase, colBase, nxt * BK1,
                         sb + ((nxt % ST1) * STG1_BYTES), tid);
        }
        cp_commit();
        stage = (stage + 1 == ST1) ? 0 : stage + 1;
    }

    int mrow = rowBase + wm * 64 + (lane >> 2);
    int ncol = colBase + wn * 32 + 2 * (lane & 3);

#pragma unroll
    for (int mi = 0; mi < 4; mi++) {
        int m0 = mrow + mi * 16;
        float s0 = 0.f, s1 = 0.f;
#pragma unroll
        for (int nj = 0; nj < 4; nj++) {
            int n = ncol + nj * 8;
            float e00 = __expf(acc[mi][nj][0]);
            float e01 = __expf(acc[mi][nj][1]);
            float e10 = __expf(acc[mi][nj][2]);
            float e11 = __expf(acc[mi][nj][3]);
            s0 += e00 + e01;
            s1 += e10 + e11;
            *reinterpret_cast<__nv_bfloat162*>(Cb + (size_t)m0 * MCOLS + n) =
                __floats2bfloat162_rn(e00, e01);
            *reinterpret_cast<__nv_bfloat162*>(Cb + (size_t)(m0 + 8) * MCOLS + n) =
                __floats2bfloat162_rn(e10, e11);
        }
        // fixed-order lane reduce (4 lanes share each row)
        s0 += __shfl_xor_sync(0xffffffffu, s0, 1);
        s0 += __shfl_xor_sync(0xffffffffu, s0, 2);
        s1 += __shfl_xor_sync(0xffffffffu, s1, 1);
        s1 += __shfl_xor_sync(0xffffffffu, s1, 2);
        if ((lane & 3) == 0) {
            int slot = blockIdx.x * 4 + wn;       // 32 coltiles x 4 warps = 128
            part[(size_t)m0 * 128 + slot]       = s0;
            part[(size_t)(m0 + 8) * 128 + slot] = s1;
        }
    }
}

// ===========================================================================
// GEMM2: fp8 e4m3 mma.sync, 128x128 CTA tile, BK=128 (bytes), 256 thr, 3 stages
//   out = (Scol[col] + acc/4096) / Zrow[row]; Scol reduced from partials in-CTA
// ===========================================================================
#define BM2 128
#define BN2 128
#define BK2 128
#define TPB2 256
#define ST2 3
#define A2_BYTES 16384
#define B2_BYTES 16384
#define STG2_BYTES (A2_BYTES + B2_BYTES)
#define SMEM2_BYTES (ST2 * STG2_BYTES)

static __device__ __forceinline__ void issue_stage2(
    const uint8_t* __restrict__ A, const uint8_t* __restrict__ B,
    int rowBase, int colBase, int k0, uint32_t sbase, int tid) {
    uint32_t sA = sbase;
    uint32_t sB = sbase + A2_BYTES;
#pragma unroll
    for (int i = 0; i < 4; i++) {
        int l = tid + i * TPB2;
        int r = l >> 3, c = l & 7;
        uint32_t off = sw128((uint32_t)(r * 128 + c * 16));
        cp16(sA + off, A + (size_t)(rowBase + r) * MCOLS + k0 + c * 16);
        cp16(sB + off, B + (size_t)(colBase + r) * MCOLS + k0 + c * 16);
    }
}

__global__ void __launch_bounds__(TPB2)
gemm2_fp8(const uint8_t* __restrict__ A, const uint8_t* __restrict__ B,
          float* __restrict__ C,
          const float* __restrict__ ScolPart, const float* __restrict__ Zrow) {
    extern __shared__ __align__(1024) char smem[];
    uint32_t sb = smem_u32(smem);
    int tid = threadIdx.x;
    int wid = tid >> 5, lane = tid & 31;
    int wm = wid >> 1, wn = wid & 1;        // 4x2 warp grid, warp = 32m x 64n
    int rowBase = blockIdx.y * BM2;
    int colBase = blockIdx.x * BN2;
    const int nIter = MCOLS / BK2;          // 32

#pragma unroll
    for (int s = 0; s < ST2 - 1; s++) {
        issue_stage2(A, B, rowBase, colBase, s * BK2, sb + s * STG2_BYTES, tid);
        cp_commit();
    }

    float acc[2][8][4];
#pragma unroll
    for (int i = 0; i < 2; i++)
#pragma unroll
        for (int j = 0; j < 8; j++)
#pragma unroll
            for (int k = 0; k < 4; k++) acc[i][j][k] = 0.f;

    int arow = wm * 32 + (lane & 15);
    int acolb = (lane >> 4) << 4;
    int brow = wn * 64 + ((lane >> 4) << 3) + (lane & 7);
    int bcolb = ((lane >> 3) & 1) << 4;

    int stage = 0;
    for (int it = 0; it < nIter; ++it) {
        cp_wait<ST2 - 2>();
        __syncthreads();
        uint32_t baseA = sb + stage * STG2_BYTES;
        uint32_t baseB = baseA + A2_BYTES;

#pragma unroll
        for (int ks = 0; ks < 4; ks++) {   // 4 x k32 fp8 per 128B chunk
            uint32_t af[2][4];
#pragma unroll
            for (int mi = 0; mi < 2; mi++) {
                uint32_t off = sw128((uint32_t)((arow + mi * 16) * 128 + ks * 32 + acolb));
                ldmatrix_x4(af[mi], baseA + off);
            }
            uint32_t bf[4][4];
#pragma unroll
            for (int ni = 0; ni < 4; ni++) {
                uint32_t off = sw128((uint32_t)((brow + ni * 16) * 128 + ks * 32 + bcolb));
                ldmatrix_x4(bf[ni], baseB + off);
            }
#pragma unroll
            for (int mi = 0; mi < 2; mi++)
#pragma unroll
                for (int ni = 0; ni < 4; ni++) {
                    mma_fp8(acc[mi][2 * ni], af[mi], &bf[ni][0]);
                    mma_fp8(acc[mi][2 * ni + 1], af[mi], &bf[ni][2]);
                }
        }

        int nxt = it + ST2 - 1;
        if (nxt < nIter) {
            issue_stage2(A, B, rowBase, colBase, nxt * BK2,
                         sb + ((nxt % ST2) * STG2_BYTES), tid);
        }
        cp_commit();
        stage = (stage + 1 == ST2) ? 0 : stage + 1;
    }

    // Scol reduction into smem (safe: all cp.async drained)
    cp_wait<0>();
    __syncthreads();
    float* sS = reinterpret_cast<float*>(smem);
    if (tid < BN2) {
        float s0 = 0.f, s1 = 0.f, s2 = 0.f, s3 = 0.f;
        const float* p = ScolPart + colBase + tid;
#pragma unroll
        for (int i = 0; i < 128; i += 4) {
            s0 += p[(size_t)i * DDIM];
            s1 += p[(size_t)(i + 1) * DDIM];
            s2 += p[(size_t)(i + 2) * DDIM];
            s3 += p[(size_t)(i + 3) * DDIM];
        }
        sS[tid] = (s0 + s1) + (s2 + s3);
    }
    __syncthreads();

    const float inv4096 = 1.0f / 4096.0f;
    int mrow = rowBase + wm * 32 + (lane >> 2);
    int ncol = colBase + wn * 64 + 2 * (lane & 3);
#pragma unroll
    for (int mi = 0; mi < 2; mi++) {
        int m0 = mrow + mi * 16;
        float rz0 = 1.0f / Zrow[m0];
        float rz1 = 1.0f / Zrow[m0 + 8];
#pragma unroll
        for (int nj = 0; nj < 8; nj++) {
            int n = ncol + nj * 8;
            float s0 = sS[n - colBase], s1 = sS[n - colBase + 1];
            float2 v0, v1;
            v0.x = (s0 + acc[mi][nj][0] * inv4096) * rz0;
            v0.y = (s1 + acc[mi][nj][1] * inv4096) * rz0;
            v1.x = (s0 + acc[mi][nj][2] * inv4096) * rz1;
            v1.y = (s1 + acc[mi][nj][3] * inv4096) * rz1;
            *reinterpret_cast<float2*>(C + (size_t)m0 * DDIM + n) = v0;
            *reinterpret_cast<float2*>(C + (size_t)(m0 + 8) * DDIM + n) = v1;
        }
    }
}

// ---------------------------------------------------------------------------
// Elementwise / reduction kernels
// ---------------------------------------------------------------------------
__global__ void conv_HK(const float* __restrict__ H, const float* __restrict__ K,
                        __nv_bfloat16* __restrict__ Hb, __nv_bfloat16* __restrict__ Kb) {
    const int n4 = NROWS * DDIM / 4;
    int i = blockIdx.x * blockDim.x + threadIdx.x;
    const float* src;
    __nv_bfloat16* dst;
    float scale;
    if (i < n4) { src = H; dst = Hb; scale = 1.0f / 32.0f; }
    else        { src = K; dst = Kb; scale = 1.0f; i -= n4; }
    float4 v = reinterpret_cast<const float4*>(src)[i];
    __nv_bfloat162 a = __floats2bfloat162_rn(v.x * scale, v.y * scale);
    __nv_bfloat162 b = __floats2bfloat162_rn(v.z * scale, v.w * scale);
    reinterpret_cast<__nv_bfloat162*>(dst)[2 * i] = a;
    reinterpret_cast<__nv_bfloat162*>(dst)[2 * i + 1] = b;
}

// V^T (e4m3) + per-row-tile column partial sums (single pass over V)
__global__ void transposeV(const float* __restrict__ V, uint8_t* __restrict__ Vt,
                           float* __restrict__ partc) {
    __shared__ float tile[32][33];
    __shared__ float red[8][32];
    int d0 = blockIdx.x * 32, m0 = blockIdx.y * 32;
    int tx = threadIdx.x, ty = threadIdx.y;  // 32 x 8
#pragma unroll
    for (int j = 0; j < 32; j += 8)
        tile[ty + j][tx] = V[(size_t)(m0 + ty + j) * DDIM + d0 + tx];
    __syncthreads();
    // fp8 transpose: thread handles (d_local = ty*4 + tx/8, m = 4*(tx&7)..+3)
    {
        int dl = ty * 4 + (tx >> 3);
        int ml = 4 * (tx & 7);
        uint32_t w = pack_e4m3x4(tile[ml][dl], tile[ml + 1][dl],
                                 tile[ml + 2][dl], tile[ml + 3][dl]);
        *reinterpret_cast<uint32_t*>(Vt + (size_t)(d0 + dl) * MCOLS + m0 + ml) = w;
    }
    // column partials: sum over the 32 m-rows for each d = tx
    float s = (tile[ty * 4 + 0][tx] + tile[ty * 4 + 1][tx]) +
              (tile[ty * 4 + 2][tx] + tile[ty * 4 + 3][tx]);
    red[ty][tx] = s;
    __syncthreads();
    if (ty == 0) {
        float t = 0.f;
#pragma unroll
        for (int i = 0; i < 8; i++) t += red[i][tx];
        partc[(size_t)blockIdx.y * DDIM + d0 + tx] = t;
    }
}

static __device__ __forceinline__ float warp_red_sum(float v) {
#pragma unroll
    for (int o = 16; o > 0; o >>= 1) v += __shfl_xor_sync(0xffffffffu, v, o);
    return v;
}

// warp-per-row, coalesced over 128 contiguous slots
__global__ void reduce_rsum(const float* __restrict__ part, float* __restrict__ rsum) {
    int w = threadIdx.x >> 5, lane = threadIdx.x & 31;
    int r = blockIdx.x * 8 + w;
    const float* p = part + (size_t)r * 128;
    float s = p[lane] + p[lane + 32] + p[lane + 64] + p[lane + 96];
    s = warp_red_sum(s);
    if (lane == 0) rsum[r] = s;
}

// fast expm1 for small non-negative x: cubic Taylor, guard to expm1f
static __device__ __forceinline__ float expm1_fast(float x) {
    float p = x * (1.0f + x * (0.5f + x * 0.16666667f));
    return (x > 0.0625f) ? expm1f(x) : p;
}

__global__ void build_e(const __nv_bfloat16* __restrict__ expsc,
                        const float* __restrict__ mask,
                        const float* __restrict__ rsum,
                        uint8_t* __restrict__ e, float* __restrict__ zrow) {
    __shared__ float red[8];
    int n = blockIdx.x, t = threadIdx.x;
    int wid = t >> 5, lid = t & 31;
    const __nv_bfloat162* srow =
        reinterpret_cast<const __nv_bfloat162*>(expsc + (size_t)n * MCOLS);
    const float4* mrow = reinterpret_cast<const float4*>(mask + (size_t)n * MCOLS);
    uint32_t* erow = reinterpret_cast<uint32_t*>(e + (size_t)n * MCOLS);
    float inv = 1.0f / rsum[n];
    float z = 0.f;
#pragma unroll
    for (int i = 0; i < 4; i++) {
        int idx = t + i * 256;
        float4 m = mrow[idx];
        __nv_bfloat162 p0 = srow[2 * idx];
        __nv_bfloat162 p1 = srow[2 * idx + 1];
        float e0 = expm1_fast(__low2float(p0)  * inv * m.x);
        float e1 = expm1_fast(__high2float(p0) * inv * m.y);
        float e2 = expm1_fast(__low2float(p1)  * inv * m.z);
        float e3 = expm1_fast(__high2float(p1) * inv * m.w);
        z += (e0 + e1) + (e2 + e3);
        erow[idx] = pack_e4m3x4(e0 * 4096.0f, e1 * 4096.0f,
                                e2 * 4096.0f, e3 * 4096.0f);
    }
    z = warp_red_sum(z);
    if (lid == 0) red[wid] = z;
    __syncthreads();
    if (t == 0) {
        float acc = 0.f;
#pragma unroll
        for (int i = 0; i < 8; i++) acc += red[i];
        zrow[n] = (float)MCOLS + acc;
    }
}

// ---------------------------------------------------------------------------
// Launch
// ---------------------------------------------------------------------------
extern "C" void kernel_launch(void* const* d_in, const int* in_sizes, int n_in,
                              void* d_out, int out_size) {
    const float* H   = (const float*)d_in[0];
    const float* K   = (const float*)d_in[1];
    const float* V   = (const float*)d_in[2];
    const float* Msk = (const float*)d_in[3];
    float* out = (float*)d_out;

    void *hb, *kb, *vt, *es, *ee, *rs, *zz, *part, *partc;
    cudaGetSymbolAddress(&hb, g_Hb);
    cudaGetSymbolAddress(&kb, g_Kb);
    cudaGetSymbolAddress(&vt, g_Vt);
    cudaGetSymbolAddress(&es, g_expsc);
    cudaGetSymbolAddress(&ee, g_e);
    cudaGetSymbolAddress(&rs, g_rsum);
    cudaGetSymbolAddress(&zz, g_z);
    cudaGetSymbolAddress(&part, g_part);
    cudaGetSymbolAddress(&partc, g_partc);

    cudaFuncSetAttribute(gemm1_bf16, cudaFuncAttributeMaxDynamicSharedMemorySize,
                         SMEM1_BYTES);
    cudaFuncSetAttribute(gemm2_fp8, cudaFuncAttributeMaxDynamicSharedMemorySize,
                         SMEM2_BYTES);

    // Stage 0: bf16 conversions + V^T(e4m3) + fused colsum partials
    conv_HK<<<2 * (NROWS * DDIM / 4) / 256, 256>>>(H, K, (__nv_bfloat16*)hb,
                                                   (__nv_bfloat16*)kb);
    transposeV<<<dim3(DDIM / 32, MCOLS / 32), dim3(32, 8)>>>(V, (uint8_t*)vt,
                                                             (float*)partc);

    // Stage 1: expsc = bf16(exp(H/32 @ K^T)) + row-sum partials (fused epilogue)
    gemm1_bf16<<<dim3(MCOLS / BN1, NROWS / BM1), TPB1, SMEM1_BYTES>>>(
        (const __nv_bfloat16*)hb, (const __nv_bfloat16*)kb,
        (__nv_bfloat16*)es, (float*)part);
    reduce_rsum<<<NROWS / 8, 256>>>((const float*)part, (float*)rs);

    // Stage 2: e = e4m3(expm1(softmax1 * mask) * 4096); z = M + sum(e)
    build_e<<<NROWS, 256>>>((const __nv_bfloat16*)es, Msk, (const float*)rs,
                            (uint8_t*)ee, (float*)zz);

    // Stage 3: out = (colsum(V) + (e @ V)/4096) / z   (fp8 tensor cores)
    gemm2_fp8<<<dim3(DDIM / BN2, NROWS / BM2), TPB2, SMEM2_BYTES>>>(
        (const uint8_t*)ee, (const uint8_t*)vt, out,
        (const float*)partc, (const float*)zz);
}

// round 9
// speedup vs baseline: 1.1226x; 1.1226x over previous
#include <cuda_runtime.h>
#include <cuda_fp16.h>
#include <cstdint>
#include <cstddef>

// Problem dims (fixed)
#define NROWS 4096
#define MCOLS 4096
#define DDIM  1024
#define E_SCALE 256.0f

// ---------------------------------------------------------------------------
// Scratch (__device__ globals — allocation-free contract)
// ---------------------------------------------------------------------------
__device__ __half g_Hh[(size_t)NROWS * DDIM];     // H * (1/32) in fp16
__device__ __half g_Kh[(size_t)MCOLS * DDIM];     // K in fp16
__device__ __half g_Vt[(size_t)DDIM * MCOLS];     // V^T in fp16 (K-major)
__device__ __half g_expsc[(size_t)NROWS * MCOLS]; // exp(scores) fp16
__device__ __half g_e[(size_t)NROWS * MCOLS];     // expm1(p*mask)*256 fp16
__device__ float g_rsum[NROWS];
__device__ float g_z[NROWS];
__device__ float g_part[(size_t)NROWS * 128];  // GEMM1 row-sum partials [row][slot]
__device__ float g_partc[128 * DDIM];          // V colsum partials (128 row-tiles)

static __device__ __forceinline__ uint32_t smem_u32(const void* p) {
    uint32_t a;
    asm("{ .reg .u64 t; cvta.to.shared.u64 t, %1; cvt.u32.u64 %0, t; }"
        : "=r"(a) : "l"(p));
    return a;
}

static __device__ __forceinline__ uint32_t sw128(uint32_t off) {
    return off ^ ((off >> 3) & 0x70);
}

static __device__ __forceinline__ void cp16(uint32_t saddr, const void* gptr) {
    asm volatile("cp.async.cg.shared.global [%0], [%1], 16;"
                 :: "r"(saddr), "l"(gptr));
}

static __device__ __forceinline__ void cp_commit() {
    asm volatile("cp.async.commit_group;");
}

template <int N>
static __device__ __forceinline__ void cp_wait() {
    asm volatile("cp.async.wait_group %0;" :: "n"(N));
}

static __device__ __forceinline__ void ldmatrix_x4(uint32_t* r, uint32_t saddr) {
    asm volatile("ldmatrix.sync.aligned.m8n8.x4.shared.b16 {%0,%1,%2,%3}, [%4];"
                 : "=r"(r[0]), "=r"(r[1]), "=r"(r[2]), "=r"(r[3]) : "r"(saddr));
}

// fp16-accumulate HMMA (2x issue rate vs f32-acc on legacy tensor path)
static __device__ __forceinline__ void mma_h(uint32_t* d, const uint32_t* a,
                                             const uint32_t* b) {
    asm volatile(
        "mma.sync.aligned.m16n8k16.row.col.f16.f16.f16.f16 "
        "{%0,%1}, {%2,%3,%4,%5}, {%6,%7}, {%0,%1};"
        : "+r"(d[0]), "+r"(d[1])
        : "r"(a[0]), "r"(a[1]), "r"(a[2]), "r"(a[3]), "r"(b[0]), "r"(b[1]));
}

// ===========================================================================
// GEMM1: fp16 mma, 256(M) x 128(N) CTA tile, BK=64, 512 thr, 4 stages
//   epilogue: expsc = fp16(exp(acc)); deterministic row-sum partials
// ===========================================================================
#define BM1 256
#define BN1 128
#define BK1 64
#define TPB1 512
#define ST1 4
#define A1_BYTES 32768
#define B1_BYTES 16384
#define STG1_BYTES (A1_BYTES + B1_BYTES)
#define SMEM1_BYTES (ST1 * STG1_BYTES)

static __device__ __forceinline__ void issue_stage1(
    const __half* __restrict__ A, const __half* __restrict__ B,
    int rowBase, int colBase, int k0, uint32_t sbase, int tid) {
    uint32_t sA = sbase;
    uint32_t sB = sbase + A1_BYTES;
#pragma unroll
    for (int i = 0; i < 4; i++) {
        int l = tid + i * TPB1;
        int r = l >> 3, c = l & 7;
        uint32_t off = sw128((uint32_t)(r * 128 + c * 16));
        cp16(sA + off, A + (size_t)(rowBase + r) * DDIM + k0 + c * 8);
    }
#pragma unroll
    for (int i = 0; i < 2; i++) {
        int l = tid + i * TPB1;
        int r = l >> 3, c = l & 7;
        uint32_t off = sw128((uint32_t)(r * 128 + c * 16));
        cp16(sB + off, B + (size_t)(colBase + r) * DDIM + k0 + c * 8);
    }
}

__global__ void __launch_bounds__(TPB1, 1)
gemm1_h(const __half* __restrict__ A, const __half* __restrict__ B,
        __half* __restrict__ Cb, float* __restrict__ part) {
    extern __shared__ __align__(1024) char smem[];
    uint32_t sb = smem_u32(smem);
    int tid = threadIdx.x;
    int wid = tid >> 5, lane = tid & 31;
    int wm = wid >> 2, wn = wid & 3;        // 4x4 warp grid, warp = 64m x 32n
    int rowBase = blockIdx.y * BM1;
    int colBase = blockIdx.x * BN1;
    const int nIter = DDIM / BK1;

#pragma unroll
    for (int s = 0; s < ST1 - 1; s++) {
        issue_stage1(A, B, rowBase, colBase, s * BK1, sb + s * STG1_BYTES, tid);
        cp_commit();
    }

    uint32_t acc[4][4][2];
#pragma unroll
    for (int i = 0; i < 4; i++)
#pragma unroll
        for (int j = 0; j < 4; j++) { acc[i][j][0] = 0u; acc[i][j][1] = 0u; }

    int arow = wm * 64 + (lane & 15);
    int acolb = (lane >> 4) << 4;
    int brow = wn * 32 + ((lane >> 4) << 3) + (lane & 7);
    int bcolb = ((lane >> 3) & 1) << 4;

    int stage = 0;
    for (int it = 0; it < nIter; ++it) {
        cp_wait<ST1 - 2>();
        __syncthreads();
        uint32_t baseA = sb + stage * STG1_BYTES;
        uint32_t baseB = baseA + A1_BYTES;

#pragma unroll
        for (int ks = 0; ks < 4; ks++) {
            uint32_t af[4][4];
#pragma unroll
            for (int mi = 0; mi < 4; mi++) {
                uint32_t off = sw128((uint32_t)((arow + mi * 16) * 128 + ks * 32 + acolb));
                ldmatrix_x4(af[mi], baseA + off);
            }
            uint32_t bf[2][4];
#pragma unroll
            for (int ni = 0; ni < 2; ni++) {
                uint32_t off = sw128((uint32_t)((brow + ni * 16) * 128 + ks * 32 + bcolb));
                ldmatrix_x4(bf[ni], baseB + off);
            }
#pragma unroll
            for (int mi = 0; mi < 4; mi++)
#pragma unroll
                for (int ni = 0; ni < 2; ni++) {
                    mma_h(acc[mi][2 * ni], af[mi], &bf[ni][0]);
                    mma_h(acc[mi][2 * ni + 1], af[mi], &bf[ni][2]);
                }
        }

        int nxt = it + ST1 - 1;
        if (nxt < nIter) {
            issue_stage1(A, B, rowBase, colBase, nxt * BK1,
                         sb + ((nxt % ST1) * STG1_BYTES), tid);
        }
        cp_commit();
        stage = (stage + 1 == ST1) ? 0 : stage + 1;
    }

    int mrow = rowBase + wm * 64 + (lane >> 2);
    int ncol = colBase + wn * 32 + 2 * (lane & 3);

#pragma unroll
    for (int mi = 0; mi < 4; mi++) {
        int m0 = mrow + mi * 16;
        float s0 = 0.f, s1 = 0.f;
#pragma unroll
        for (int nj = 0; nj < 4; nj++) {
            int n = ncol + nj * 8;
            float2 r0 = __half22float2(*reinterpret_cast<__half2*>(&acc[mi][nj][0]));
            float2 r1 = __half22float2(*reinterpret_cast<__half2*>(&acc[mi][nj][1]));
            float e00 = __expf(r0.x);
            float e01 = __expf(r0.y);
            float e10 = __expf(r1.x);
            float e11 = __expf(r1.y);
            s0 += e00 + e01;
            s1 += e10 + e11;
            *reinterpret_cast<__half2*>(Cb + (size_t)m0 * MCOLS + n) =
                __floats2half2_rn(e00, e01);
            *reinterpret_cast<__half2*>(Cb + (size_t)(m0 + 8) * MCOLS + n) =
                __floats2half2_rn(e10, e11);
        }
        // fixed-order lane reduce (4 lanes share each row)
        s0 += __shfl_xor_sync(0xffffffffu, s0, 1);
        s0 += __shfl_xor_sync(0xffffffffu, s0, 2);
        s1 += __shfl_xor_sync(0xffffffffu, s1, 1);
        s1 += __shfl_xor_sync(0xffffffffu, s1, 2);
        if ((lane & 3) == 0) {
            int slot = blockIdx.x * 4 + wn;       // 32 coltiles x 4 warps = 128
            part[(size_t)m0 * 128 + slot]       = s0;
            part[(size_t)(m0 + 8) * 128 + slot] = s1;
        }
    }
}

// ===========================================================================
// GEMM2: fp16 mma, 128x128 CTA tile, BK=64, 256 thr, 3 stages
//   out = (Scol[col] + acc/256) / Zrow[row]; Scol reduced from partials in-CTA
// ===========================================================================
#define BM2 128
#define BN2 128
#define BK2 64
#define TPB2 256
#define ST2 3
#define A2_BYTES 16384
#define B2_BYTES 16384
#define STG2_BYTES (A2_BYTES + B2_BYTES)
#define SMEM2_BYTES (ST2 * STG2_BYTES)

static __device__ __forceinline__ void issue_stage2(
    const __half* __restrict__ A, const __half* __restrict__ B,
    int rowBase, int colBase, int k0, uint32_t sbase, int tid) {
    uint32_t sA = sbase;
    uint32_t sB = sbase + A2_BYTES;
#pragma unroll
    for (int i = 0; i < 4; i++) {
        int l = tid + i * TPB2;
        int r = l >> 3, c = l & 7;
        uint32_t off = sw128((uint32_t)(r * 128 + c * 16));
        cp16(sA + off, A + (size_t)(rowBase + r) * MCOLS + k0 + c * 8);
        cp16(sB + off, B + (size_t)(colBase + r) * MCOLS + k0 + c * 8);
    }
}

__global__ void __launch_bounds__(TPB2)
gemm2_h(const __half* __restrict__ A, const __half* __restrict__ B,
        float* __restrict__ C,
        const float* __restrict__ ScolPart, const float* __restrict__ Zrow) {
    extern __shared__ __align__(1024) char smem[];
    uint32_t sb = smem_u32(smem);
    int tid = threadIdx.x;
    int wid = tid >> 5, lane = tid & 31;
    int wm = wid >> 1, wn = wid & 1;        // 4x2 warp grid, warp = 32m x 64n
    int rowBase = blockIdx.y * BM2;
    int colBase = blockIdx.x * BN2;
    const int nIter = MCOLS / BK2;          // 64

#pragma unroll
    for (int s = 0; s < ST2 - 1; s++) {
        issue_stage2(A, B, rowBase, colBase, s * BK2, sb + s * STG2_BYTES, tid);
        cp_commit();
    }

    uint32_t acc[2][8][2];
#pragma unroll
    for (int i = 0; i < 2; i++)
#pragma unroll
        for (int j = 0; j < 8; j++) { acc[i][j][0] = 0u; acc[i][j][1] = 0u; }

    int arow = wm * 32 + (lane & 15);
    int acolb = (lane >> 4) << 4;
    int brow = wn * 64 + ((lane >> 4) << 3) + (lane & 7);
    int bcolb = ((lane >> 3) & 1) << 4;

    int stage = 0;
    for (int it = 0; it < nIter; ++it) {
        cp_wait<ST2 - 2>();
        __syncthreads();
        uint32_t baseA = sb + stage * STG2_BYTES;
        uint32_t baseB = baseA + A2_BYTES;

#pragma unroll
        for (int ks = 0; ks < 4; ks++) {
            uint32_t af[2][4];
#pragma unroll
            for (int mi = 0; mi < 2; mi++) {
                uint32_t off = sw128((uint32_t)((arow + mi * 16) * 128 + ks * 32 + acolb));
                ldmatrix_x4(af[mi], baseA + off);
            }
            uint32_t bf[4][4];
#pragma unroll
            for (int ni = 0; ni < 4; ni++) {
                uint32_t off = sw128((uint32_t)((brow + ni * 16) * 128 + ks * 32 + bcolb));
                ldmatrix_x4(bf[ni], baseB + off);
            }
#pragma unroll
            for (int mi = 0; mi < 2; mi++)
#pragma unroll
                for (int ni = 0; ni < 4; ni++) {
                    mma_h(acc[mi][2 * ni], af[mi], &bf[ni][0]);
                    mma_h(acc[mi][2 * ni + 1], af[mi], &bf[ni][2]);
                }
        }

        int nxt = it + ST2 - 1;
        if (nxt < nIter) {
            issue_stage2(A, B, rowBase, colBase, nxt * BK2,
                         sb + ((nxt % ST2) * STG2_BYTES), tid);
        }
        cp_commit();
        stage = (stage + 1 == ST2) ? 0 : stage + 1;
    }

    // Scol reduction into smem (safe: all cp.async drained)
    cp_wait<0>();
    __syncthreads();
    float* sS = reinterpret_cast<float*>(smem);
    if (tid < BN2) {
        float s0 = 0.f, s1 = 0.f, s2 = 0.f, s3 = 0.f;
        const float* p = ScolPart + colBase + tid;
#pragma unroll
        for (int i = 0; i < 128; i += 4) {
            s0 += p[(size_t)i * DDIM];
            s1 += p[(size_t)(i + 1) * DDIM];
            s2 += p[(size_t)(i + 2) * DDIM];
            s3 += p[(size_t)(i + 3) * DDIM];
        }
        sS[tid] = (s0 + s1) + (s2 + s3);
    }
    __syncthreads();

    const float invE = 1.0f / E_SCALE;
    int mrow = rowBase + wm * 32 + (lane >> 2);
    int ncol = colBase + wn * 64 + 2 * (lane & 3);
#pragma unroll
    for (int mi = 0; mi < 2; mi++) {
        int m0 = mrow + mi * 16;
        float rz0 = 1.0f / Zrow[m0];
        float rz1 = 1.0f / Zrow[m0 + 8];
#pragma unroll
        for (int nj = 0; nj < 8; nj++) {
            int n = ncol + nj * 8;
            float s0 = sS[n - colBase], s1 = sS[n - colBase + 1];
            float2 r0 = __half22float2(*reinterpret_cast<__half2*>(&acc[mi][nj][0]));
            float2 r1 = __half22float2(*reinterpret_cast<__half2*>(&acc[mi][nj][1]));
            float2 v0, v1;
            v0.x = (s0 + r0.x * invE) * rz0;
            v0.y = (s1 + r0.y * invE) * rz0;
            v1.x = (s0 + r1.x * invE) * rz1;
            v1.y = (s1 + r1.y * invE) * rz1;
            *reinterpret_cast<float2*>(C + (size_t)m0 * DDIM + n) = v0;
            *reinterpret_cast<float2*>(C + (size_t)(m0 + 8) * DDIM + n) = v1;
        }
    }
}

// ---------------------------------------------------------------------------
// Elementwise / reduction kernels
// ---------------------------------------------------------------------------
__global__ void conv_HK(const float* __restrict__ H, const float* __restrict__ K,
                        __half* __restrict__ Hh, __half* __restrict__ Kh) {
    const int n4 = NROWS * DDIM / 4;
    int i = blockIdx.x * blockDim.x + threadIdx.x;
    const float* src;
    __half* dst;
    float scale;
    if (i < n4) { src = H; dst = Hh; scale = 1.0f / 32.0f; }
    else        { src = K; dst = Kh; scale = 1.0f; i -= n4; }
    float4 v = reinterpret_cast<const float4*>(src)[i];
    __half2 a = __floats2half2_rn(v.x * scale, v.y * scale);
    __half2 b = __floats2half2_rn(v.z * scale, v.w * scale);
    reinterpret_cast<__half2*>(dst)[2 * i] = a;
    reinterpret_cast<__half2*>(dst)[2 * i + 1] = b;
}

// V^T (fp16) + per-row-tile column partial sums (single pass over V)
__global__ void transposeV(const float* __restrict__ V, __half* __restrict__ Vt,
                           float* __restrict__ partc) {
    __shared__ float tile[32][33];
    __shared__ float red[8][32];
    int d0 = blockIdx.x * 32, m0 = blockIdx.y * 32;
    int tx = threadIdx.x, ty = threadIdx.y;  // 32 x 8
#pragma unroll
    for (int j = 0; j < 32; j += 8)
        tile[ty + j][tx] = V[(size_t)(m0 + ty + j) * DDIM + d0 + tx];
    __syncthreads();
    // fp16 transpose: thread handles (d_local = ty*4 + tx/8, m = 4*(tx&7)..+3)
    {
        int dl = ty * 4 + (tx >> 3);
        int ml = 4 * (tx & 7);
        __half2 w0 = __floats2half2_rn(tile[ml][dl], tile[ml + 1][dl]);
        __half2 w1 = __floats2half2_rn(tile[ml + 2][dl], tile[ml + 3][dl]);
        __half2* dst = reinterpret_cast<__half2*>(Vt + (size_t)(d0 + dl) * MCOLS + m0 + ml);
        dst[0] = w0;
        dst[1] = w1;
    }
    // column partials: sum over the 32 m-rows for each d = tx
    float s = (tile[ty * 4 + 0][tx] + tile[ty * 4 + 1][tx]) +
              (tile[ty * 4 + 2][tx] + tile[ty * 4 + 3][tx]);
    red[ty][tx] = s;
    __syncthreads();
    if (ty == 0) {
        float t = 0.f;
#pragma unroll
        for (int i = 0; i < 8; i++) t += red[i][tx];
        partc[(size_t)blockIdx.y * DDIM + d0 + tx] = t;
    }
}

static __device__ __forceinline__ float warp_red_sum(float v) {
#pragma unroll
    for (int o = 16; o > 0; o >>= 1) v += __shfl_xor_sync(0xffffffffu, v, o);
    return v;
}

// warp-per-row, coalesced over 128 contiguous slots
__global__ void reduce_rsum(const float* __restrict__ part, float* __restrict__ rsum) {
    int w = threadIdx.x >> 5, lane = threadIdx.x & 31;
    int r = blockIdx.x * 8 + w;
    const float* p = part + (size_t)r * 128;
    float s = p[lane] + p[lane + 32] + p[lane + 64] + p[lane + 96];
    s = warp_red_sum(s);
    if (lane == 0) rsum[r] = s;
}

// fast expm1 for small non-negative x: cubic Taylor, guard to expm1f
static __device__ __forceinline__ float expm1_fast(float x) {
    float p = x * (1.0f + x * (0.5f + x * 0.16666667f));
    return (x > 0.0625f) ? expm1f(x) : p;
}

__global__ void build_e(const __half* __restrict__ expsc,
                        const float* __restrict__ mask,
                        const float* __restrict__ rsum,
                        __half* __restrict__ e, float* __restrict__ zrow) {
    __shared__ float red[8];
    int n = blockIdx.x, t = threadIdx.x;
    int wid = t >> 5, lid = t & 31;
    const __half2* srow = reinterpret_cast<const __half2*>(expsc + (size_t)n * MCOLS);
    const float4* mrow = reinterpret_cast<const float4*>(mask + (size_t)n * MCOLS);
    __half2* erow = reinterpret_cast<__half2*>(e + (size_t)n * MCOLS);
    float inv = 1.0f / rsum[n];
    float z = 0.f;
#pragma unroll
    for (int i = 0; i < 4; i++) {
        int idx = t + i * 256;
        float4 m = mrow[idx];
        __half2 p0 = srow[2 * idx];
        __half2 p1 = srow[2 * idx + 1];
        float e0 = expm1_fast(__low2float(p0)  * inv * m.x);
        float e1 = expm1_fast(__high2float(p0) * inv * m.y);
        float e2 = expm1_fast(__low2float(p1)  * inv * m.z);
        float e3 = expm1_fast(__high2float(p1) * inv * m.w);
        z += (e0 + e1) + (e2 + e3);
        erow[2 * idx]     = __floats2half2_rn(e0 * E_SCALE, e1 * E_SCALE);
        erow[2 * idx + 1] = __floats2half2_rn(e2 * E_SCALE, e3 * E_SCALE);
    }
    z = warp_red_sum(z);
    if (lid == 0) red[wid] = z;
    __syncthreads();
    if (t == 0) {
        float acc = 0.f;
#pragma unroll
        for (int i = 0; i < 8; i++) acc += red[i];
        zrow[n] = (float)MCOLS + acc;
    }
}

// ---------------------------------------------------------------------------
// Launch
// ---------------------------------------------------------------------------
extern "C" void kernel_launch(void* const* d_in, const int* in_sizes, int n_in,
                              void* d_out, int out_size) {
    const float* H   = (const float*)d_in[0];
    const float* K   = (const float*)d_in[1];
    const float* V   = (const float*)d_in[2];
    const float* Msk = (const float*)d_in[3];
    float* out = (float*)d_out;

    void *hh, *kh, *vt, *es, *ee, *rs, *zz, *part, *partc;
    cudaGetSymbolAddress(&hh, g_Hh);
    cudaGetSymbolAddress(&kh, g_Kh);
    cudaGetSymbolAddress(&vt, g_Vt);
    cudaGetSymbolAddress(&es, g_expsc);
    cudaGetSymbolAddress(&ee, g_e);
    cudaGetSymbolAddress(&rs, g_rsum);
    cudaGetSymbolAddress(&zz, g_z);
    cudaGetSymbolAddress(&part, g_part);
    cudaGetSymbolAddress(&partc, g_partc);

    cudaFuncSetAttribute(gemm1_h, cudaFuncAttributeMaxDynamicSharedMemorySize,
                         SMEM1_BYTES);
    cudaFuncSetAttribute(gemm2_h, cudaFuncAttributeMaxDynamicSharedMemorySize,
                         SMEM2_BYTES);

    // Stage 0: fp16 conversions + V^T + fused colsum partials
    conv_HK<<<2 * (NROWS * DDIM / 4) / 256, 256>>>(H, K, (__half*)hh, (__half*)kh);
    transposeV<<<dim3(DDIM / 32, MCOLS / 32), dim3(32, 8)>>>(V, (__half*)vt,
                                                             (float*)partc);

    // Stage 1: expsc = fp16(exp(H/32 @ K^T)) + row-sum partials (fused epilogue)
    gemm1_h<<<dim3(MCOLS / BN1, NROWS / BM1), TPB1, SMEM1_BYTES>>>(
        (const __half*)hh, (const __half*)kh, (__half*)es, (float*)part);
    reduce_rsum<<<NROWS / 8, 256>>>((const float*)part, (float*)rs);

    // Stage 2: e = fp16(expm1(softmax1 * mask) * 256); z = M + sum(e)
    build_e<<<NROWS, 256>>>((const __half*)es, Msk, (const float*)rs,
                            (__half*)ee, (float*)zz);

    // Stage 3: out = (colsum(V) + (e @ V)/256) / z   (fp16-acc tensor cores)
    gemm2_h<<<dim3(DDIM / BN2, NROWS / BM2), TPB2, SMEM2_BYTES>>>(
        (const __half*)ee, (const __half*)vt, out,
        (const float*)partc, (const float*)zz);
}

// round 10
// speedup vs baseline: 1.1407x; 1.0161x over previous
#include <cuda_runtime.h>
#include <cuda_fp16.h>
#include <cstdint>
#include <cstddef>

// Problem dims (fixed)
#define NROWS 4096
#define MCOLS 4096
#define DDIM  1024
#define E_SCALE 256.0f

// ---------------------------------------------------------------------------
// Scratch (__device__ globals — allocation-free contract)
// ---------------------------------------------------------------------------
__device__ __half g_Hh[(size_t)NROWS * DDIM];     // H * (1/32) in fp16
__device__ __half g_Kh[(size_t)MCOLS * DDIM];     // K in fp16
__device__ __half g_Vt[(size_t)DDIM * MCOLS];     // V^T in fp16 (K-major)
__device__ __half g_expsc[(size_t)NROWS * MCOLS]; // exp(scores) fp16
__device__ __half g_e[(size_t)NROWS * MCOLS];     // expm1(p*mask)*256 fp16
__device__ float g_rsum[NROWS];
__device__ float g_z[NROWS];
__device__ float g_part[(size_t)NROWS * 64];   // GEMM1 row-sum partials [row][slot]
__device__ float g_partc[128 * DDIM];          // V colsum partials (128 row-tiles)

static __device__ __forceinline__ uint32_t smem_u32(const void* p) {
    uint32_t a;
    asm("{ .reg .u64 t; cvta.to.shared.u64 t, %1; cvt.u32.u64 %0, t; }"
        : "=r"(a) : "l"(p));
    return a;
}

static __device__ __forceinline__ uint32_t sw128(uint32_t off) {
    return off ^ ((off >> 3) & 0x70);
}

static __device__ __forceinline__ void cp16(uint32_t saddr, const void* gptr) {
    asm volatile("cp.async.cg.shared.global [%0], [%1], 16;"
                 :: "r"(saddr), "l"(gptr));
}

static __device__ __forceinline__ void cp_commit() {
    asm volatile("cp.async.commit_group;");
}

template <int N>
static __device__ __forceinline__ void cp_wait() {
    asm volatile("cp.async.wait_group %0;" :: "n"(N));
}

static __device__ __forceinline__ void ldmatrix_x4(uint32_t* r, uint32_t saddr) {
    asm volatile("ldmatrix.sync.aligned.m8n8.x4.shared.b16 {%0,%1,%2,%3}, [%4];"
                 : "=r"(r[0]), "=r"(r[1]), "=r"(r[2]), "=r"(r[3]) : "r"(saddr));
}

// fp16-accumulate HMMA (numerics validated R9: rel_err 8.7e-7)
static __device__ __forceinline__ void mma_h(uint32_t* d, const uint32_t* a,
                                             const uint32_t* b) {
    asm volatile(
        "mma.sync.aligned.m16n8k16.row.col.f16.f16.f16.f16 "
        "{%0,%1}, {%2,%3,%4,%5}, {%6,%7}, {%0,%1};"
        : "+r"(d[0]), "+r"(d[1])
        : "r"(a[0]), "r"(a[1]), "r"(a[2]), "r"(a[3]), "r"(b[0]), "r"(b[1]));
}

// ===========================================================================
// GEMM1: fp16 mma, 256(M) x 256(N) CTA tile, BK=64, 512 thr (16 warps 4x4,
//   warp tile 64x64 => 8 LDSM per 32 MMAs), 3-stage cp.async pipeline.
//   epilogue: expsc = fp16(exp(acc)); deterministic row-sum partials
// ===========================================================================
#define BM1 256
#define BN1 256
#define BK1 64
#define TPB1 512
#define ST1 3
#define A1_BYTES 32768             // 256 x 64 fp16
#define B1_BYTES 32768             // 256 x 64 fp16
#define STG1_BYTES (A1_BYTES + B1_BYTES)
#define SMEM1_BYTES (ST1 * STG1_BYTES)

static __device__ __forceinline__ void issue_stage1(
    const __half* __restrict__ A, const __half* __restrict__ B,
    int rowBase, int colBase, int k0, uint32_t sbase, int tid) {
    uint32_t sA = sbase;
    uint32_t sB = sbase + A1_BYTES;
#pragma unroll
    for (int i = 0; i < 4; i++) {
        int l = tid + i * TPB1;
        int r = l >> 3, c = l & 7;
        uint32_t off = sw128((uint32_t)(r * 128 + c * 16));
        cp16(sA + off, A + (size_t)(rowBase + r) * DDIM + k0 + c * 8);
        cp16(sB + off, B + (size_t)(colBase + r) * DDIM + k0 + c * 8);
    }
}

__global__ void __launch_bounds__(TPB1, 1)
gemm1_h(const __half* __restrict__ A, const __half* __restrict__ B,
        __half* __restrict__ Cb, float* __restrict__ part) {
    extern __shared__ __align__(1024) char smem[];
    uint32_t sb = smem_u32(smem);
    int tid = threadIdx.x;
    int wid = tid >> 5, lane = tid & 31;
    int wm = wid >> 2, wn = wid & 3;        // 4x4 warp grid, warp = 64m x 64n
    int rowBase = blockIdx.y * BM1;
    int colBase = blockIdx.x * BN1;
    const int nIter = DDIM / BK1;           // 16

#pragma unroll
    for (int s = 0; s < ST1 - 1; s++) {
        issue_stage1(A, B, rowBase, colBase, s * BK1, sb + s * STG1_BYTES, tid);
        cp_commit();
    }

    uint32_t acc[4][8][2];
#pragma unroll
    for (int i = 0; i < 4; i++)
#pragma unroll
        for (int j = 0; j < 8; j++) { acc[i][j][0] = 0u; acc[i][j][1] = 0u; }

    int arow = wm * 64 + (lane & 15);
    int acolb = (lane >> 4) << 4;
    int brow = wn * 64 + ((lane >> 4) << 3) + (lane & 7);
    int bcolb = ((lane >> 3) & 1) << 4;

    int stage = 0;
    for (int it = 0; it < nIter; ++it) {
        cp_wait<ST1 - 2>();
        __syncthreads();
        uint32_t baseA = sb + stage * STG1_BYTES;
        uint32_t baseB = baseA + A1_BYTES;

#pragma unroll
        for (int ks = 0; ks < 4; ks++) {
            uint32_t af[4][4];
#pragma unroll
            for (int mi = 0; mi < 4; mi++) {
                uint32_t off = sw128((uint32_t)((arow + mi * 16) * 128 + ks * 32 + acolb));
                ldmatrix_x4(af[mi], baseA + off);
            }
            uint32_t bf[4][4];
#pragma unroll
            for (int ni = 0; ni < 4; ni++) {
                uint32_t off = sw128((uint32_t)((brow + ni * 16) * 128 + ks * 32 + bcolb));
                ldmatrix_x4(bf[ni], baseB + off);
            }
#pragma unroll
            for (int mi = 0; mi < 4; mi++)
#pragma unroll
                for (int ni = 0; ni < 4; ni++) {
                    mma_h(acc[mi][2 * ni], af[mi], &bf[ni][0]);
                    mma_h(acc[mi][2 * ni + 1], af[mi], &bf[ni][2]);
                }
        }

        int nxt = it + ST1 - 1;
        if (nxt < nIter) {
            issue_stage1(A, B, rowBase, colBase, nxt * BK1,
                         sb + ((nxt % ST1) * STG1_BYTES), tid);
        }
        cp_commit();
        stage = (stage + 1 == ST1) ? 0 : stage + 1;
    }

    int mrow = rowBase + wm * 64 + (lane >> 2);
    int ncol = colBase + wn * 64 + 2 * (lane & 3);

#pragma unroll
    for (int mi = 0; mi < 4; mi++) {
        int m0 = mrow + mi * 16;
        float s0 = 0.f, s1 = 0.f;
#pragma unroll
        for (int nj = 0; nj < 8; nj++) {
            int n = ncol + nj * 8;
            float2 r0 = __half22float2(*reinterpret_cast<__half2*>(&acc[mi][nj][0]));
            float2 r1 = __half22float2(*reinterpret_cast<__half2*>(&acc[mi][nj][1]));
            float e00 = __expf(r0.x);
            float e01 = __expf(r0.y);
            float e10 = __expf(r1.x);
            float e11 = __expf(r1.y);
            s0 += e00 + e01;
            s1 += e10 + e11;
            *reinterpret_cast<__half2*>(Cb + (size_t)m0 * MCOLS + n) =
                __floats2half2_rn(e00, e01);
            *reinterpret_cast<__half2*>(Cb + (size_t)(m0 + 8) * MCOLS + n) =
                __floats2half2_rn(e10, e11);
        }
        // fixed-order lane reduce (4 lanes share each row)
        s0 += __shfl_xor_sync(0xffffffffu, s0, 1);
        s0 += __shfl_xor_sync(0xffffffffu, s0, 2);
        s1 += __shfl_xor_sync(0xffffffffu, s1, 1);
        s1 += __shfl_xor_sync(0xffffffffu, s1, 2);
        if ((lane & 3) == 0) {
            int slot = blockIdx.x * 4 + wn;       // 16 coltiles x 4 warps = 64
            part[(size_t)m0 * 64 + slot]       = s0;
            part[(size_t)(m0 + 8) * 64 + slot] = s1;
        }
    }
}

// ===========================================================================
// GEMM2: fp16 mma, 128(M) x 256(N) CTA tile, BK=64, 256 thr (8 warps 2x4,
//   warp tile 64x64), 3 stages. out = (Scol[col] + acc/256) / Zrow[row]
// ===========================================================================
#define BM2 128
#define BN2 256
#define BK2 64
#define TPB2 256
#define ST2 3
#define A2_BYTES 16384             // 128 x 64 fp16
#define B2_BYTES 32768             // 256 x 64 fp16
#define STG2_BYTES (A2_BYTES + B2_BYTES)
#define SMEM2_BYTES (ST2 * STG2_BYTES)

static __device__ __forceinline__ void issue_stage2(
    const __half* __restrict__ A, const __half* __restrict__ B,
    int rowBase, int colBase, int k0, uint32_t sbase, int tid) {
    uint32_t sA = sbase;
    uint32_t sB = sbase + A2_BYTES;
#pragma unroll
    for (int i = 0; i < 4; i++) {      // A: 1024 chunks
        int l = tid + i * TPB2;
        int r = l >> 3, c = l & 7;
        uint32_t off = sw128((uint32_t)(r * 128 + c * 16));
        cp16(sA + off, A + (size_t)(rowBase + r) * MCOLS + k0 + c * 8);
    }
#pragma unroll
    for (int i = 0; i < 8; i++) {      // B: 2048 chunks
        int l = tid + i * TPB2;
        int r = l >> 3, c = l & 7;
        uint32_t off = sw128((uint32_t)(r * 128 + c * 16));
        cp16(sB + off, B + (size_t)(colBase + r) * MCOLS + k0 + c * 8);
    }
}

__global__ void __launch_bounds__(TPB2, 1)
gemm2_h(const __half* __restrict__ A, const __half* __restrict__ B,
        float* __restrict__ C,
        const float* __restrict__ ScolPart, const float* __restrict__ Zrow) {
    extern __shared__ __align__(1024) char smem[];
    uint32_t sb = smem_u32(smem);
    int tid = threadIdx.x;
    int wid = tid >> 5, lane = tid & 31;
    int wm = wid >> 2, wn = wid & 3;        // 2x4 warp grid, warp = 64m x 64n
    int rowBase = blockIdx.y * BM2;
    int colBase = blockIdx.x * BN2;
    const int nIter = MCOLS / BK2;          // 64

#pragma unroll
    for (int s = 0; s < ST2 - 1; s++) {
        issue_stage2(A, B, rowBase, colBase, s * BK2, sb + s * STG2_BYTES, tid);
        cp_commit();
    }

    uint32_t acc[4][8][2];
#pragma unroll
    for (int i = 0; i < 4; i++)
#pragma unroll
        for (int j = 0; j < 8; j++) { acc[i][j][0] = 0u; acc[i][j][1] = 0u; }

    int arow = wm * 64 + (lane & 15);
    int acolb = (lane >> 4) << 4;
    int brow = wn * 64 + ((lane >> 4) << 3) + (lane & 7);
    int bcolb = ((lane >> 3) & 1) << 4;

    int stage = 0;
    for (int it = 0; it < nIter; ++it) {
        cp_wait<ST2 - 2>();
        __syncthreads();
        uint32_t baseA = sb + stage * STG2_BYTES;
        uint32_t baseB = baseA + A2_BYTES;

#pragma unroll
        for (int ks = 0; ks < 4; ks++) {
            uint32_t af[4][4];
#pragma unroll
            for (int mi = 0; mi < 4; mi++) {
                uint32_t off = sw128((uint32_t)((arow + mi * 16) * 128 + ks * 32 + acolb));
                ldmatrix_x4(af[mi], baseA + off);
            }
            uint32_t bf[4][4];
#pragma unroll
            for (int ni = 0; ni < 4; ni++) {
                uint32_t off = sw128((uint32_t)((brow + ni * 16) * 128 + ks * 32 + bcolb));
                ldmatrix_x4(bf[ni], baseB + off);
            }
#pragma unroll
            for (int mi = 0; mi < 4; mi++)
#pragma unroll
                for (int ni = 0; ni < 4; ni++) {
                    mma_h(acc[mi][2 * ni], af[mi], &bf[ni][0]);
                    mma_h(acc[mi][2 * ni + 1], af[mi], &bf[ni][2]);
                }
        }

        int nxt = it + ST2 - 1;
        if (nxt < nIter) {
            issue_stage2(A, B, rowBase, colBase, nxt * BK2,
                         sb + ((nxt % ST2) * STG2_BYTES), tid);
        }
        cp_commit();
        stage = (stage + 1 == ST2) ? 0 : stage + 1;
    }

    // Scol reduction into smem (safe: all cp.async drained)
    cp_wait<0>();
    __syncthreads();
    float* sS = reinterpret_cast<float*>(smem);
    {
        float s0 = 0.f, s1 = 0.f, s2 = 0.f, s3 = 0.f;
        const float* p = ScolPart + colBase + tid;
#pragma unroll
        for (int i = 0; i < 128; i += 4) {
            s0 += p[(size_t)i * DDIM];
            s1 += p[(size_t)(i + 1) * DDIM];
            s2 += p[(size_t)(i + 2) * DDIM];
            s3 += p[(size_t)(i + 3) * DDIM];
        }
        sS[tid] = (s0 + s1) + (s2 + s3);
    }
    __syncthreads();

    const float invE = 1.0f / E_SCALE;
    int mrow = rowBase + wm * 64 + (lane >> 2);
    int ncol = colBase + wn * 64 + 2 * (lane & 3);
#pragma unroll
    for (int mi = 0; mi < 4; mi++) {
        int m0 = mrow + mi * 16;
        float rz0 = 1.0f / Zrow[m0];
        float rz1 = 1.0f / Zrow[m0 + 8];
#pragma unroll
        for (int nj = 0; nj < 8; nj++) {
            int n = ncol + nj * 8;
            float s0 = sS[n - colBase], s1 = sS[n - colBase + 1];
            float2 r0 = __half22float2(*reinterpret_cast<__half2*>(&acc[mi][nj][0]));
            float2 r1 = __half22float2(*reinterpret_cast<__half2*>(&acc[mi][nj][1]));
            float2 v0, v1;
            v0.x = (s0 + r0.x * invE) * rz0;
            v0.y = (s1 + r0.y * invE) * rz0;
            v1.x = (s0 + r1.x * invE) * rz1;
            v1.y = (s1 + r1.y * invE) * rz1;
            *reinterpret_cast<float2*>(C + (size_t)m0 * DDIM + n) = v0;
            *reinterpret_cast<float2*>(C + (size_t)(m0 + 8) * DDIM + n) = v1;
        }
    }
}

// ---------------------------------------------------------------------------
// Elementwise / reduction kernels
// ---------------------------------------------------------------------------
__global__ void conv_HK(const float* __restrict__ H, const float* __restrict__ K,
                        __half* __restrict__ Hh, __half* __restrict__ Kh) {
    const int n4 = NROWS * DDIM / 4;
    int i = blockIdx.x * blockDim.x + threadIdx.x;
    const float* src;
    __half* dst;
    float scale;
    if (i < n4) { src = H; dst = Hh; scale = 1.0f / 32.0f; }
    else        { src = K; dst = Kh; scale = 1.0f; i -= n4; }
    float4 v = reinterpret_cast<const float4*>(src)[i];
    __half2 a = __floats2half2_rn(v.x * scale, v.y * scale);
    __half2 b = __floats2half2_rn(v.z * scale, v.w * scale);
    reinterpret_cast<__half2*>(dst)[2 * i] = a;
    reinterpret_cast<__half2*>(dst)[2 * i + 1] = b;
}

// V^T (fp16) + per-row-tile column partial sums (single pass over V)
__global__ void transposeV(const float* __restrict__ V, __half* __restrict__ Vt,
                           float* __restrict__ partc) {
    __shared__ float tile[32][33];
    __shared__ float red[8][32];
    int d0 = blockIdx.x * 32, m0 = blockIdx.y * 32;
    int tx = threadIdx.x, ty = threadIdx.y;  // 32 x 8
#pragma unroll
    for (int j = 0; j < 32; j += 8)
        tile[ty + j][tx] = V[(size_t)(m0 + ty + j) * DDIM + d0 + tx];
    __syncthreads();
    // fp16 transpose: thread handles (d_local = ty*4 + tx/8, m = 4*(tx&7)..+3)
    {
        int dl = ty * 4 + (tx >> 3);
        int ml = 4 * (tx & 7);
        __half2 w0 = __floats2half2_rn(tile[ml][dl], tile[ml + 1][dl]);
        __half2 w1 = __floats2half2_rn(tile[ml + 2][dl], tile[ml + 3][dl]);
        __half2* dst = reinterpret_cast<__half2*>(Vt + (size_t)(d0 + dl) * MCOLS + m0 + ml);
        dst[0] = w0;
        dst[1] = w1;
    }
    // column partials: sum over the 32 m-rows for each d = tx
    float s = (tile[ty * 4 + 0][tx] + tile[ty * 4 + 1][tx]) +
              (tile[ty * 4 + 2][tx] + tile[ty * 4 + 3][tx]);
    red[ty][tx] = s;
    __syncthreads();
    if (ty == 0) {
        float t = 0.f;
#pragma unroll
        for (int i = 0; i < 8; i++) t += red[i][tx];
        partc[(size_t)blockIdx.y * DDIM + d0 + tx] = t;
    }
}

static __device__ __forceinline__ float warp_red_sum(float v) {
#pragma unroll
    for (int o = 16; o > 0; o >>= 1) v += __shfl_xor_sync(0xffffffffu, v, o);
    return v;
}

// warp-per-row, coalesced over 64 contiguous slots
__global__ void reduce_rsum(const float* __restrict__ part, float* __restrict__ rsum) {
    int w = threadIdx.x >> 5, lane = threadIdx.x & 31;
    int r = blockIdx.x * 8 + w;
    const float* p = part + (size_t)r * 64;
    float s = p[lane] + p[lane + 32];
    s = warp_red_sum(s);
    if (lane == 0) rsum[r] = s;
}

// fast expm1 for small non-negative x: cubic Taylor, guard to expm1f
static __device__ __forceinline__ float expm1_fast(float x) {
    float p = x * (1.0f + x * (0.5f + x * 0.16666667f));
    return (x > 0.0625f) ? expm1f(x) : p;
}

__global__ void build_e(const __half* __restrict__ expsc,
                        const float* __restrict__ mask,
                        const float* __restrict__ rsum,
                        __half* __restrict__ e, float* __restrict__ zrow) {
    __shared__ float red[8];
    int n = blockIdx.x, t = threadIdx.x;
    int wid = t >> 5, lid = t & 31;
    const __half2* srow = reinterpret_cast<const __half2*>(expsc + (size_t)n * MCOLS);
    const float4* mrow = reinterpret_cast<const float4*>(mask + (size_t)n * MCOLS);
    __half2* erow = reinterpret_cast<__half2*>(e + (size_t)n * MCOLS);
    float inv = 1.0f / rsum[n];
    float z = 0.f;
#pragma unroll
    for (int i = 0; i < 4; i++) {
        int idx = t + i * 256;
        float4 m = mrow[idx];
        __half2 p0 = srow[2 * idx];
        __half2 p1 = srow[2 * idx + 1];
        float e0 = expm1_fast(__low2float(p0)  * inv * m.x);
        float e1 = expm1_fast(__high2float(p0) * inv * m.y);
        float e2 = expm1_fast(__low2float(p1)  * inv * m.z);
        float e3 = expm1_fast(__high2float(p1) * inv * m.w);
        z += (e0 + e1) + (e2 + e3);
        erow[2 * idx]     = __floats2half2_rn(e0 * E_SCALE, e1 * E_SCALE);
        erow[2 * idx + 1] = __floats2half2_rn(e2 * E_SCALE, e3 * E_SCALE);
    }
    z = warp_red_sum(z);
    if (lid == 0) red[wid] = z;
    __syncthreads();
    if (t == 0) {
        float acc = 0.f;
#pragma unroll
        for (int i = 0; i < 8; i++) acc += red[i];
        zrow[n] = (float)MCOLS + acc;
    }
}

// ---------------------------------------------------------------------------
// Launch
// ---------------------------------------------------------------------------
extern "C" void kernel_launch(void* const* d_in, const int* in_sizes, int n_in,
                              void* d_out, int out_size) {
    const float* H   = (const float*)d_in[0];
    const float* K   = (const float*)d_in[1];
    const float* V   = (const float*)d_in[2];
    const float* Msk = (const float*)d_in[3];
    float* out = (float*)d_out;

    void *hh, *kh, *vt, *es, *ee, *rs, *zz, *part, *partc;
    cudaGetSymbolAddress(&hh, g_Hh);
    cudaGetSymbolAddress(&kh, g_Kh);
    cudaGetSymbolAddress(&vt, g_Vt);
    cudaGetSymbolAddress(&es, g_expsc);
    cudaGetSymbolAddress(&ee, g_e);
    cudaGetSymbolAddress(&rs, g_rsum);
    cudaGetSymbolAddress(&zz, g_z);
    cudaGetSymbolAddress(&part, g_part);
    cudaGetSymbolAddress(&partc, g_partc);

    cudaFuncSetAttribute(gemm1_h, cudaFuncAttributeMaxDynamicSharedMemorySize,
                         SMEM1_BYTES);
    cudaFuncSetAttribute(gemm2_h, cudaFuncAttributeMaxDynamicSharedMemorySize,
                         SMEM2_BYTES);

    // Stage 0: fp16 conversions + V^T + fused colsum partials
    conv_HK<<<2 * (NROWS * DDIM / 4) / 256, 256>>>(H, K, (__half*)hh, (__half*)kh);
    transposeV<<<dim3(DDIM / 32, MCOLS / 32), dim3(32, 8)>>>(V, (__half*)vt,
                                                             (float*)partc);

    // Stage 1: expsc = fp16(exp(H/32 @ K^T)) + row-sum partials (fused epilogue)
    gemm1_h<<<dim3(MCOLS / BN1, NROWS / BM1), TPB1, SMEM1_BYTES>>>(
        (const __half*)hh, (const __half*)kh, (__half*)es, (float*)part);
    reduce_rsum<<<NROWS / 8, 256>>>((const float*)part, (float*)rs);

    // Stage 2: e = fp16(expm1(softmax1 * mask) * 256); z = M + sum(e)
    build_e<<<NROWS, 256>>>((const __half*)es, Msk, (const float*)rs,
                            (__half*)ee, (float*)zz);

    // Stage 3: out = (colsum(V) + (e @ V)/256) / z   (fp16-acc tensor cores)
    gemm2_h<<<dim3(DDIM / BN2, NROWS / BM2), TPB2, SMEM2_BYTES>>>(
        (const __half*)ee, (const __half*)vt, out,
        (const float*)partc, (const float*)zz);
}